// round 10
// baseline (speedup 1.0000x reference)
#include <cuda_runtime.h>

#define NSTEP  25
#define NIN    9
#define NHID   100

__global__ __launch_bounds__(64) void snn_kernel(
    const float* __restrict__ x,
    const float* __restrict__ W1,
    const float* __restrict__ b1,
    const float* __restrict__ W2,
    const float* __restrict__ b2,
    float* __restrict__ out,
    int batch)
{
    // W1 padded to 12 floats/row: [w0..w8, b1, 0, 0] -> 3x LDS.128 per neuron
    __shared__ float4 sW1[NHID * 3];
    __shared__ float2 sW2[NHID];   // (W2[0][h], W2[1][h])
    __shared__ float  sb2[2];

    {
        float* sW1f = (float*)sW1;
        for (int h = threadIdx.x; h < NHID; h += blockDim.x) {
#pragma unroll
            for (int i = 0; i < NIN; i++) sW1f[h * 12 + i] = W1[h * NIN + i];
            sW1f[h * 12 + 9]  = b1[h];
            sW1f[h * 12 + 10] = 0.0f;
            sW1f[h * 12 + 11] = 0.0f;
            sW2[h] = make_float2(W2[h], W2[NHID + h]);
        }
        if (threadIdx.x < 2) sb2[threadIdx.x] = b2[threadIdx.x];
    }
    __syncthreads();

    int b = blockIdx.x * blockDim.x + threadIdx.x;
    if (b >= batch) return;

    float xv[NIN];
#pragma unroll
    for (int i = 0; i < NIN; i++) xv[i] = __ldg(&x[(size_t)b * NIN + i]);

    float acc0[NSTEP], acc1[NSTEP];
#pragma unroll
    for (int t = 0; t < NSTEP; t++) { acc0[t] = 0.0f; acc1[t] = 0.0f; }

    // 25 groups of 4 neurons; 4 independent recurrence chains per group.
    for (int g = 0; g < NHID / 4; g++) {
        const int h = g * 4;
        float c[4], cm1[4];
        float2 w[4];
#pragma unroll
        for (int j = 0; j < 4; j++) {
            float4 a0 = sW1[(h + j) * 3 + 0];
            float4 a1 = sW1[(h + j) * 3 + 1];
            float4 a2 = sW1[(h + j) * 3 + 2];
            float cc = a2.y;                   // bias in padded slot 9
            cc = fmaf(xv[0], a0.x, cc); cc = fmaf(xv[1], a0.y, cc);
            cc = fmaf(xv[2], a0.z, cc); cc = fmaf(xv[3], a0.w, cc);
            cc = fmaf(xv[4], a1.x, cc); cc = fmaf(xv[5], a1.y, cc);
            cc = fmaf(xv[6], a1.z, cc); cc = fmaf(xv[7], a1.w, cc);
            cc = fmaf(xv[8], a2.x, cc);
            c[j]   = cc;
            cm1[j] = cc - 1.0f;
            w[j]   = sW2[h + j];
        }

        // m_0 = 0, first reset = 0 -> addend cr starts at c
        float m[4]  = {0.f, 0.f, 0.f, 0.f};
        float cr[4] = {c[0], c[1], c[2], c[3]};

        // Per neuron-step (6 instr; fma 5 rt-cyc, alu 6 rt-cyc):
        //   m  = 0.95*m + cr          (FFMA-imm, fma rt1; cr = c - spike_prev)
        //   p  = m > 1                (FSETP, alu)
        //   cr = p ? c-1 : c          (FSEL, alu, pred-as-data)
        //   r  = p ? 1 : 0            (FSEL, alu)
        //   acc0 += r*w0              (FFMA, fma rt2)
        //   acc1 += r*w1              (FFMA, fma rt2)
#pragma unroll
        for (int t = 0; t < NSTEP; t++) {
#pragma unroll
            for (int j = 0; j < 4; j++) {
                m[j] = fmaf(0.95f, m[j], cr[j]);
                bool p = (m[j] > 1.0f);
                cr[j]  = p ? cm1[j] : c[j];
                float r = p ? 1.0f : 0.0f;
                acc0[t] = fmaf(r, w[j].x, acc0[t]);
                acc1[t] = fmaf(r, w[j].y, acc1[t]);
            }
        }
    }

    // Layer-2 LIF recurrence + record mem2 each step
    const float bb0 = sb2[0], bb1 = sb2[1];
    float m20 = 0.0f, m21 = 0.0f;
    float2* outv = (float2*)out;
#pragma unroll
    for (int t = 0; t < NSTEP; t++) {
        float rr0 = (m20 > 1.0f) ? 1.0f : 0.0f;   // reset from PREVIOUS mem2
        float rr1 = (m21 > 1.0f) ? 1.0f : 0.0f;
        m20 = fmaf(0.95f, m20, acc0[t] + bb0) - rr0;
        m21 = fmaf(0.95f, m21, acc1[t] + bb1) - rr1;
        outv[(size_t)t * batch + b] = make_float2(m20, m21);
    }
}

extern "C" void kernel_launch(void* const* d_in, const int* in_sizes, int n_in,
                              void* d_out, int out_size)
{
    const float* x  = (const float*)d_in[0];
    const float* W1 = (const float*)d_in[1];
    const float* b1 = (const float*)d_in[2];
    const float* W2 = (const float*)d_in[3];
    const float* b2 = (const float*)d_in[4];
    float* out = (float*)d_out;

    int batch = in_sizes[0] / NIN;
    const int threads = 64;
    int blocks = (batch + threads - 1) / threads;
    snn_kernel<<<blocks, threads>>>(x, W1, b1, W2, b2, out, batch);
}

// round 11
// speedup vs baseline: 1.2393x; 1.2393x over previous
#include <cuda_runtime.h>

#define NSTEP  25
#define NIN    9
#define NHID   100
#define NGRP   (NHID / 4)   // 25 groups of 4 neurons

__global__ __launch_bounds__(64) void snn_kernel(
    const float* __restrict__ x,
    const float* __restrict__ W1,
    const float* __restrict__ b1,
    const float* __restrict__ W2,
    const float* __restrict__ b2,
    float* __restrict__ out,
    int batch)
{
    // W1 padded to 12 floats/row: [w0..w8, b1, 0, 0] -> 3x LDS.128 per neuron
    __shared__ float4 sW1[NHID * 3];
    __shared__ float2 sTab[NGRP * 16];  // [group][pattern] -> (sum w2_0, sum w2_1)
    __shared__ float  sb2[2];

    {
        float* sW1f = (float*)sW1;
        for (int h = threadIdx.x; h < NHID; h += blockDim.x) {
#pragma unroll
            for (int i = 0; i < NIN; i++) sW1f[h * 12 + i] = W1[h * NIN + i];
            sW1f[h * 12 + 9]  = b1[h];
            sW1f[h * 12 + 10] = 0.0f;
            sW1f[h * 12 + 11] = 0.0f;
        }
        // Pattern table: for group g, pattern p (4 bits, bit j = neuron g*4+j
        // spiking), entry = (sum_j w2[0][h], sum_j w2[1][h]) over set bits.
        for (int e = threadIdx.x; e < NGRP * 16; e += blockDim.x) {
            int g = e >> 4, p = e & 15;
            float s0 = 0.0f, s1 = 0.0f;
#pragma unroll
            for (int j = 0; j < 4; j++) {
                if (p & (1 << j)) {
                    s0 += W2[g * 4 + j];
                    s1 += W2[NHID + g * 4 + j];
                }
            }
            sTab[e] = make_float2(s0, s1);
        }
        if (threadIdx.x < 2) sb2[threadIdx.x] = b2[threadIdx.x];
    }
    __syncthreads();

    int b = blockIdx.x * blockDim.x + threadIdx.x;
    if (b >= batch) return;

    float xv[NIN];
#pragma unroll
    for (int i = 0; i < NIN; i++) xv[i] = __ldg(&x[(size_t)b * NIN + i]);

    float acc0[NSTEP], acc1[NSTEP];
#pragma unroll
    for (int t = 0; t < NSTEP; t++) { acc0[t] = 0.0f; acc1[t] = 0.0f; }

    // 25 groups of 4 neurons; 4 independent recurrence chains per group.
    for (int g = 0; g < NGRP; g++) {
        const int h = g * 4;
        float c[4];
#pragma unroll
        for (int j = 0; j < 4; j++) {
            float4 a0 = sW1[(h + j) * 3 + 0];
            float4 a1 = sW1[(h + j) * 3 + 1];
            float4 a2 = sW1[(h + j) * 3 + 2];
            float cc = a2.y;                   // bias in padded slot 9
            cc = fmaf(xv[0], a0.x, cc); cc = fmaf(xv[1], a0.y, cc);
            cc = fmaf(xv[2], a0.z, cc); cc = fmaf(xv[3], a0.w, cc);
            cc = fmaf(xv[4], a1.x, cc); cc = fmaf(xv[5], a1.y, cc);
            cc = fmaf(xv[6], a1.z, cc); cc = fmaf(xv[7], a1.w, cc);
            cc = fmaf(xv[8], a2.x, cc);
            c[j] = cc;
        }
        const float2* gt = &sTab[g * 16];

        float m0 = 0.f, m1 = 0.f, m2 = 0.f, m3 = 0.f;   // membranes
        float r0 = 0.f, r1 = 0.f, r2 = 0.f, r3 = 0.f;   // spikes (float 0/1)

        // Per group-step: EXACT R3 membrane math (4x FFMA-imm + FADD, 4x FSET),
        // then nibble fold (3x FFMA-imm) + F2I + LDS.64 + 2x FADD.
        // fma rt-cycles 19 (was 28); instr count unchanged.
#pragma unroll
        for (int t = 0; t < NSTEP; t++) {
            m0 = fmaf(0.95f, m0, c[0]) - r0;
            m1 = fmaf(0.95f, m1, c[1]) - r1;
            m2 = fmaf(0.95f, m2, c[2]) - r2;
            m3 = fmaf(0.95f, m3, c[3]) - r3;
            asm("set.gt.f32.f32 %0, %1, 0f3F800000;" : "=f"(r0) : "f"(m0));
            asm("set.gt.f32.f32 %0, %1, 0f3F800000;" : "=f"(r1) : "f"(m1));
            asm("set.gt.f32.f32 %0, %1, 0f3F800000;" : "=f"(r2) : "f"(m2));
            asm("set.gt.f32.f32 %0, %1, 0f3F800000;" : "=f"(r3) : "f"(m3));
            // idx = r0 + 2*r1 + 4*r2 + 8*r3 via 3 FFMA-imm (exact in fp32)
            float idxf = fmaf(r3, 2.0f, r2);
            idxf = fmaf(idxf, 2.0f, r1);
            idxf = fmaf(idxf, 2.0f, r0);
            int idx = __float2int_rn(idxf);
            float2 v = gt[idx];
            acc0[t] += v.x;
            acc1[t] += v.y;
        }
    }

    // Layer-2 LIF recurrence + record mem2 each step
    const float bb0 = sb2[0], bb1 = sb2[1];
    float m20 = 0.0f, m21 = 0.0f;
    float2* outv = (float2*)out;
#pragma unroll
    for (int t = 0; t < NSTEP; t++) {
        float rr0, rr1;                        // reset from PREVIOUS mem2
        asm("set.gt.f32.f32 %0, %1, 0f3F800000;" : "=f"(rr0) : "f"(m20));
        asm("set.gt.f32.f32 %0, %1, 0f3F800000;" : "=f"(rr1) : "f"(m21));
        m20 = fmaf(0.95f, m20, acc0[t] + bb0) - rr0;
        m21 = fmaf(0.95f, m21, acc1[t] + bb1) - rr1;
        outv[(size_t)t * batch + b] = make_float2(m20, m21);
    }
}

extern "C" void kernel_launch(void* const* d_in, const int* in_sizes, int n_in,
                              void* d_out, int out_size)
{
    const float* x  = (const float*)d_in[0];
    const float* W1 = (const float*)d_in[1];
    const float* b1 = (const float*)d_in[2];
    const float* W2 = (const float*)d_in[3];
    const float* b2 = (const float*)d_in[4];
    float* out = (float*)d_out;

    int batch = in_sizes[0] / NIN;
    const int threads = 64;
    int blocks = (batch + threads - 1) / threads;
    snn_kernel<<<blocks, threads>>>(x, W1, b1, W2, b2, out, batch);
}